// round 2
// baseline (speedup 1.0000x reference)
#include <cuda_runtime.h>

// B=8192, A=26, NUM_TYPES=3, ANCHOR_DIM=31 (20 anchors, 10 vis, 1 class)
// triples = 8192*26*3 = 638976, each 31 contiguous floats.
#define ANCHOR_DIM 31
#define KSTEPS 10
#define EPSF 1e-9f

constexpr int TRIPLES_PER_BLOCK = 128;
constexpr int THREADS = 128;
constexpr int FLOATS_PER_BLOCK = TRIPLES_PER_BLOCK * ANCHOR_DIM;  // 3968
constexpr int VEC_PER_BLOCK = FLOATS_PER_BLOCK / 4;               // 992
constexpr int MAX_BLOCKS = 8192;

// Per-block partial sums (double) + completion counter. No init kernel needed:
// every block unconditionally writes its own slot, and the counter self-resets.
__device__ double g_part0[MAX_BLOCKS];
__device__ double g_part1[MAX_BLOCKS];
__device__ double g_part2[MAX_BLOCKS];
__device__ unsigned int g_count = 0;

__global__ void __launch_bounds__(THREADS)
loss_kernel(const float* __restrict__ pred, const float* __restrict__ gt,
            float* __restrict__ out) {
    __shared__ float sp[FLOATS_PER_BLOCK];
    __shared__ float sg[FLOATS_PER_BLOCK];

    // Stage this block's contiguous chunk with float4 LDGs.
    size_t base = (size_t)blockIdx.x * FLOATS_PER_BLOCK;
    const float4* p4 = reinterpret_cast<const float4*>(pred + base);
    const float4* g4 = reinterpret_cast<const float4*>(gt + base);
    float4* sp4 = reinterpret_cast<float4*>(sp);
    float4* sg4 = reinterpret_cast<float4*>(sg);
#pragma unroll 4
    for (int i = threadIdx.x; i < VEC_PER_BLOCK; i += THREADS) {
        sp4[i] = p4[i];
        sg4[i] = g4[i];
    }
    __syncthreads();

    // One triple per thread. SMEM stride 31 coprime with 32 banks -> conflict-free.
    const float* tp = sp + threadIdx.x * ANCHOR_DIM;
    const float* tg = sg + threadIdx.x * ANCHOR_DIM;

    // BCE terms in base-2 on the MUFU pipe (440K warp MUFU instrs total ~ 3us);
    // convert to natural log once at the end.
    float s0 = 0.0f, s2 = 0.0f;
    float gvis[KSTEPS];
#pragma unroll
    for (int j = 0; j < KSTEPS; j++) {
        float g = tg[2 * KSTEPS + j];
        float p = tp[2 * KSTEPS + j];
        gvis[j] = g;
        s0 += g * __log2f(p + EPSF) + (1.0f - g + EPSF) * __log2f(1.0f - p + EPSF);
    }
    float gcls = tg[3 * KSTEPS];
    float pcls = tp[3 * KSTEPS];
    float s1 = gcls * __log2f(pcls + EPSF) + (1.0f - gcls) * __log2f(1.0f - pcls + EPSF);

    // |c * d| == |c| * |d| exactly (IEEE rounding is sign-symmetric); c >= 0 here.
#pragma unroll
    for (int j = 0; j < KSTEPS; j++) {
        float c = gcls * gvis[j];
        s2 += c * (fabsf(tp[j] - tg[j]) + fabsf(tp[KSTEPS + j] - tg[KSTEPS + j]));
    }

#pragma unroll
    for (int o = 16; o > 0; o >>= 1) {
        s0 += __shfl_xor_sync(0xffffffffu, s0, o);
        s1 += __shfl_xor_sync(0xffffffffu, s1, o);
        s2 += __shfl_xor_sync(0xffffffffu, s2, o);
    }

    __shared__ float red[3][THREADS / 32];
    int wid = threadIdx.x >> 5;
    int lid = threadIdx.x & 31;
    if (lid == 0) { red[0][wid] = s0; red[1][wid] = s1; red[2][wid] = s2; }
    __syncthreads();

    __shared__ bool is_last;
    if (threadIdx.x == 0) {
        float a0 = 0.0f, a1 = 0.0f, a2 = 0.0f;
#pragma unroll
        for (int w = 0; w < THREADS / 32; w++) { a0 += red[0][w]; a1 += red[1][w]; a2 += red[2][w]; }
        g_part0[blockIdx.x] = (double)a0;
        g_part1[blockIdx.x] = (double)a1;
        g_part2[blockIdx.x] = (double)a2;
        __threadfence();  // make partials visible before signaling completion
        unsigned int c = atomicAdd(&g_count, 1u);
        is_last = (c == gridDim.x - 1);
    }
    __syncthreads();

    if (!is_last) return;

    // Last block: reduce all per-block partials and write the 4 outputs.
    __threadfence();  // acquire side: see all other blocks' partial writes
    double a0 = 0.0, a1 = 0.0, a2 = 0.0;
    for (int i = threadIdx.x; i < gridDim.x; i += THREADS) {
        a0 += g_part0[i];
        a1 += g_part1[i];
        a2 += g_part2[i];
    }
#pragma unroll
    for (int o = 16; o > 0; o >>= 1) {
        a0 += __shfl_xor_sync(0xffffffffu, a0, o);
        a1 += __shfl_xor_sync(0xffffffffu, a1, o);
        a2 += __shfl_xor_sync(0xffffffffu, a2, o);
    }
    __shared__ double dred[3][THREADS / 32];
    if (lid == 0) { dred[0][wid] = a0; dred[1][wid] = a1; dred[2][wid] = a2; }
    __syncthreads();
    if (threadIdx.x == 0) {
        double t0 = 0.0, t1 = 0.0, t2 = 0.0;
#pragma unroll
        for (int w = 0; w < THREADS / 32; w++) { t0 += dred[0][w]; t1 += dred[1][w]; t2 += dred[2][w]; }
        const double LN2 = 0.6931471805599453;
        float l0 = (float)(-t0 * LN2 / (double)KSTEPS);
        float l1 = (float)(-t1 * LN2);
        float l2 = (float)(t2);
        out[0] = l0 + l1 + l2;
        out[1] = l0;
        out[2] = l1;
        out[3] = l2;
        g_count = 0;  // self-reset -> deterministic across graph replays
    }
}

extern "C" void kernel_launch(void* const* d_in, const int* in_sizes, int n_in,
                              void* d_out, int out_size) {
    const float* pred = (const float*)d_in[0];
    const float* gt   = (const float*)d_in[1];
    // d_in[2..5] (hcam/pitch) are unused by the reference.

    int total_floats = in_sizes[0];             // 19,808,256
    int triples = total_floats / ANCHOR_DIM;    // 638,976
    int blocks = triples / TRIPLES_PER_BLOCK;   // 4,992 (exact)

    loss_kernel<<<blocks, THREADS>>>(pred, gt, (float*)d_out);
}

// round 3
// speedup vs baseline: 1.3192x; 1.3192x over previous
#include <cuda_runtime.h>
#include <cstdint>

// B=8192, A=26, NUM_TYPES=3, ANCHOR_DIM=31 (20 anchors, 10 vis, 1 class)
// triples = 8192*26*3 = 638976, each 31 contiguous floats.
#define ANCHOR_DIM 31
#define KSTEPS 10
#define EPSF 1e-9f

constexpr int THREADS = 128;
constexpr int TRIPLES_PER_TILE = 128;                 // one triple per thread per tile
constexpr int FPT = TRIPLES_PER_TILE * ANCHOR_DIM;    // 3968 floats per array per tile
constexpr int V4 = FPT / 4;                           // 992 float4s
constexpr int TILES_PER_BLOCK = 4;
constexpr int STAGES = 2;
constexpr int SMEM_BYTES = STAGES * 2 * FPT * 4;      // 63488 B (dynamic)
constexpr int MAX_BLOCKS = 2048;

__device__ double g_part0[MAX_BLOCKS];
__device__ double g_part1[MAX_BLOCKS];
__device__ double g_part2[MAX_BLOCKS];
__device__ unsigned int g_count = 0;

__device__ __forceinline__ void cp16(float* smem_dst, const float4* gsrc) {
    uint32_t s = (uint32_t)__cvta_generic_to_shared(smem_dst);
    asm volatile("cp.async.cg.shared.global [%0], [%1], 16;" :: "r"(s), "l"(gsrc));
}

__global__ void __launch_bounds__(THREADS)
loss_kernel(const float* __restrict__ pred, const float* __restrict__ gt,
            float* __restrict__ out) {
    extern __shared__ float dsm[];
    // Layout: stage s: [pred tile FPT floats][gt tile FPT floats]
    int tile0 = blockIdx.x * TILES_PER_BLOCK;

    // Issue a tile's loads into a stage (non-blocking) and close the group.
    auto issue = [&](int tile, int stage) {
        float* sp = dsm + stage * (2 * FPT);
        float* sg = sp + FPT;
        size_t base = (size_t)tile * FPT;
        const float4* p4 = reinterpret_cast<const float4*>(pred + base);
        const float4* g4 = reinterpret_cast<const float4*>(gt + base);
        for (int i = threadIdx.x; i < V4; i += THREADS) {
            cp16(sp + 4 * i, p4 + i);
            cp16(sg + 4 * i, g4 + i);
        }
        asm volatile("cp.async.commit_group;" ::: "memory");
    };

    issue(tile0 + 0, 0);
    issue(tile0 + 1, 1);

    float s0 = 0.0f, s1 = 0.0f, s2 = 0.0f;

#pragma unroll
    for (int k = 0; k < TILES_PER_BLOCK; k++) {
        const int stage = k & 1;
        if (k == TILES_PER_BLOCK - 1) {
            asm volatile("cp.async.wait_group 0;" ::: "memory");
        } else {
            asm volatile("cp.async.wait_group 1;" ::: "memory");
        }
        __syncthreads();

        // One triple per thread. SMEM stride 31 coprime with 32 banks -> conflict-free.
        const float* tp = dsm + stage * (2 * FPT) + threadIdx.x * ANCHOR_DIM;
        const float* tg = tp + FPT;

        // BCE in base-2 on the MUFU pipe; scale by ln2 once at the very end.
        float gvis[KSTEPS];
#pragma unroll
        for (int j = 0; j < KSTEPS; j++) {
            float g = tg[2 * KSTEPS + j];
            float p = tp[2 * KSTEPS + j];
            gvis[j] = g;
            s0 += g * __log2f(p + EPSF) + (1.0f - g + EPSF) * __log2f(1.0f - p + EPSF);
        }
        float gcls = tg[3 * KSTEPS];
        float pcls = tp[3 * KSTEPS];
        s1 += gcls * __log2f(pcls + EPSF) + (1.0f - gcls) * __log2f(1.0f - pcls + EPSF);

        // |c*d| == |c|*|d| exactly; c = gcls*gvis >= 0 here.
#pragma unroll
        for (int j = 0; j < KSTEPS; j++) {
            float c = gcls * gvis[j];
            s2 += c * (fabsf(tp[j] - tg[j]) + fabsf(tp[KSTEPS + j] - tg[KSTEPS + j]));
        }

        __syncthreads();  // everyone done reading this stage before refill
        if (k + 2 < TILES_PER_BLOCK) issue(tile0 + k + 2, stage);
    }

    // Block reduction.
#pragma unroll
    for (int o = 16; o > 0; o >>= 1) {
        s0 += __shfl_xor_sync(0xffffffffu, s0, o);
        s1 += __shfl_xor_sync(0xffffffffu, s1, o);
        s2 += __shfl_xor_sync(0xffffffffu, s2, o);
    }
    __shared__ float red[3][THREADS / 32];
    int wid = threadIdx.x >> 5;
    int lid = threadIdx.x & 31;
    if (lid == 0) { red[0][wid] = s0; red[1][wid] = s1; red[2][wid] = s2; }
    __syncthreads();

    __shared__ bool is_last;
    if (threadIdx.x == 0) {
        float a0 = 0.0f, a1 = 0.0f, a2 = 0.0f;
#pragma unroll
        for (int w = 0; w < THREADS / 32; w++) { a0 += red[0][w]; a1 += red[1][w]; a2 += red[2][w]; }
        g_part0[blockIdx.x] = (double)a0;
        g_part1[blockIdx.x] = (double)a1;
        g_part2[blockIdx.x] = (double)a2;
        __threadfence();
        unsigned int c = atomicAdd(&g_count, 1u);
        is_last = (c == gridDim.x - 1);
    }
    __syncthreads();
    if (!is_last) return;

    // Last block: fold all per-block partials, write the 4 outputs.
    __threadfence();
    double a0 = 0.0, a1 = 0.0, a2 = 0.0;
    for (int i = threadIdx.x; i < gridDim.x; i += THREADS) {
        a0 += g_part0[i];
        a1 += g_part1[i];
        a2 += g_part2[i];
    }
#pragma unroll
    for (int o = 16; o > 0; o >>= 1) {
        a0 += __shfl_xor_sync(0xffffffffu, a0, o);
        a1 += __shfl_xor_sync(0xffffffffu, a1, o);
        a2 += __shfl_xor_sync(0xffffffffu, a2, o);
    }
    __shared__ double dred[3][THREADS / 32];
    if (lid == 0) { dred[0][wid] = a0; dred[1][wid] = a1; dred[2][wid] = a2; }
    __syncthreads();
    if (threadIdx.x == 0) {
        double t0 = 0.0, t1 = 0.0, t2 = 0.0;
#pragma unroll
        for (int w = 0; w < THREADS / 32; w++) { t0 += dred[0][w]; t1 += dred[1][w]; t2 += dred[2][w]; }
        const double LN2 = 0.6931471805599453;
        float l0 = (float)(-t0 * LN2 / (double)KSTEPS);
        float l1 = (float)(-t1 * LN2);
        float l2 = (float)(t2);
        out[0] = l0 + l1 + l2;
        out[1] = l0;
        out[2] = l1;
        out[3] = l2;
        g_count = 0;  // self-reset -> deterministic across graph replays
    }
}

extern "C" void kernel_launch(void* const* d_in, const int* in_sizes, int n_in,
                              void* d_out, int out_size) {
    const float* pred = (const float*)d_in[0];
    const float* gt   = (const float*)d_in[1];
    // d_in[2..5] (hcam/pitch) are unused by the reference.

    int total_floats = in_sizes[0];                         // 19,808,256
    int triples = total_floats / ANCHOR_DIM;                // 638,976
    int blocks = triples / (TRIPLES_PER_TILE * TILES_PER_BLOCK);  // 1248 exact

    // Not stream-ordered -> legal during graph capture; sticky after first call.
    cudaFuncSetAttribute(loss_kernel, cudaFuncAttributeMaxDynamicSharedMemorySize,
                         SMEM_BYTES);
    loss_kernel<<<blocks, THREADS, SMEM_BYTES>>>(pred, gt, (float*)d_out);
}